// round 4
// baseline (speedup 1.0000x reference)
#include <cuda_runtime.h>

// BoxRenderLoss, single fused launch, R4.
//
// Separable boundary-min (4 edges x 25 linspace samples):
//   min over {X0,X1}x{y_k}  = min((px-X0)^2,(px-X1)^2) + min_k (py-y_k)^2
//   min over {x_k}x{Y0,Y1}  = min((py-Y0)^2,(py-Y1)^2) + min_k (px-x_k)^2
// Nearest sample index analytic (round + clamp, probe +-1).
//
// R4 vs R3: runtime was invariant to compute changes -> attack the serial
// tail instead. Per-block f64 atomicAdd (318-cyc round trip, same-address
// serialization) replaced by contention-free plain STG of a float partial;
// single ticket atomicInc; the whole last block reduces the partials.

#define THREADS 256
#define MAX_BLOCKS 4096

__device__ float g_partial[MAX_BLOCKS];
__device__ unsigned int g_ticket = 0;   // atomicInc with wrap -> self-resetting

// min over k=0..24 of (p - (k*(1/24)*len + lo))^2, matching reference sampling.
// inv24len = 24/len (precomputed, the only MUFU use per thread).
__device__ __forceinline__ float edge_min_sq(float p, float lo, float len,
                                             float inv24len) {
    const float DB = 1.0f / 24.0f;
    float tc = (p - lo) * inv24len;                // continuous nearest index
    // NaN/inf-safe clamp (len==0 -> tc inf/NaN -> k0 in range; samples coincide)
    float k0f = fminf(fmaxf(roundf(tc), 0.0f), 24.0f);
    int k0 = (int)k0f;
    float best = 3.4e38f;
#pragma unroll
    for (int dk = -1; dk <= 1; ++dk) {
        int k = min(max(k0 + dk, 0), 24);
        float s = fmaf((float)k * DB, len, lo);    // same formula as reference
        float dd = p - s;
        best = fminf(best, dd * dd);
    }
    return best;
}

__device__ __forceinline__ float block_reduce(float val, float* ws) {
    unsigned mask = 0xffffffffu;
#pragma unroll
    for (int o = 16; o > 0; o >>= 1)
        val += __shfl_down_sync(mask, val, o);
    int lane = threadIdx.x & 31;
    int wid  = threadIdx.x >> 5;
    if (lane == 0) ws[wid] = val;
    __syncthreads();
    float v = 0.0f;
    if (wid == 0) {
        v = (lane < THREADS / 32) ? ws[lane] : 0.0f;
#pragma unroll
        for (int o = (THREADS / 32) / 2; o > 0; o >>= 1)
            v += __shfl_down_sync(mask, v, o);
    }
    return v;   // valid in warp 0 lane 0
}

__global__ __launch_bounds__(THREADS)
void box_render_loss_fused(const float4* __restrict__ boxes,
                           const float4* __restrict__ targets,
                           float* __restrict__ out,
                           int ntasks, double scale, unsigned int nblocks) {
    int t = blockIdx.x * THREADS + threadIdx.x;
    float val = 0.0f;
    if (t < ntasks) {
        int row = t % 10;          // fragment row -> px
        int d   = (t / 10) & 1;    // direction: 0 = box frags vs target, 1 = swap
        int b   = t / 20;          // pair index

        float4 A = boxes[b];
        float4 T = targets[b];
        float4 F = d ? T : A;      // fragment-source box
        float4 O = d ? A : T;      // other box

        const float DF = 1.0f / 9.0f;
        float fw = F.z - F.x, fh = F.w - F.y;
        float px = fmaf((float)row * DF, fw, F.x);

        float ow = O.z - O.x, oh = O.w - O.y;
        float inv24w = 24.0f * __frcp_rn(ow);
        float inv24h = 24.0f * __frcp_rn(oh);
        float X1 = ow + O.x;       // 1*ow + O.x, exactly as reference computes it
        float Y1 = oh + O.y;

        // x-dependent terms, hoisted across the 10 py values
        bool in_x   = (px - O.x >= 0.0f) && (O.z - px >= 0.0f);
        float dx0 = px - O.x, dx1 = px - X1;
        float vert_x = fminf(dx0 * dx0, dx1 * dx1);        // vertical edges, x part
        float dxmin  = edge_min_sq(px, O.x, ow, inv24w);   // horizontal edges, x part

#pragma unroll
        for (int fi = 0; fi < 10; ++fi) {
            float py = fmaf((float)fi * DF, fh, F.y);
            bool inside = in_x && (py - O.y >= 0.0f) && (O.w - py >= 0.0f);
            if (!inside) {
                float dymin = edge_min_sq(py, O.y, oh, inv24h);
                float dy0 = py - O.y, dy1 = py - Y1;
                float horz = fminf(dy0 * dy0, dy1 * dy1) + dxmin;
                val += fminf(vert_x + dymin, horz);
            }
        }
    }

    __shared__ float ws[THREADS / 32];
    __shared__ bool  is_last;
    float bsum = block_reduce(val, ws);

    if (threadIdx.x == 0) {
        g_partial[blockIdx.x] = bsum;    // contention-free plain store
        __threadfence();                 // make it visible GPU-wide
        // wraps back to 0 at nblocks-1 -> self-resetting across graph replays
        unsigned int ticket = atomicInc(&g_ticket, nblocks - 1u);
        is_last = (ticket == nblocks - 1u);
    }
    __syncthreads();

    if (is_last) {
        // Every prior block fenced before its inc -> partials visible at L2.
        // __ldcg bypasses L1 (this block never cached these lines anyway).
        float v = 0.0f;
        for (unsigned int i = threadIdx.x; i < nblocks; i += THREADS)
            v += __ldcg(&g_partial[i]);
        __syncthreads();                 // ws reuse hazard
        float total = block_reduce(v, ws);
        if (threadIdx.x == 0)
            out[0] = (float)((double)total * scale);
    }
}

extern "C" void kernel_launch(void* const* d_in, const int* in_sizes, int n_in,
                              void* d_out, int out_size) {
    const float4* boxes   = (const float4*)d_in[0];
    const float4* targets = (const float4*)d_in[1];
    float* out = (float*)d_out;

    int B = in_sizes[0] / 4;                 // 4096
    int ntasks = B * 20;                     // 2 directions * 10 rows
    unsigned int nblocks = (unsigned int)((ntasks + THREADS - 1) / THREADS); // 320
    if (nblocks > MAX_BLOCKS) nblocks = MAX_BLOCKS;

    double scale = 1.0 / (2.0 * (double)B * 100.0);

    box_render_loss_fused<<<nblocks, THREADS>>>(boxes, targets, out,
                                                ntasks, scale, nblocks);
}

// round 5
// speedup vs baseline: 1.1037x; 1.1037x over previous
#include <cuda_runtime.h>

// BoxRenderLoss, single fused launch, R5.
//
// Separable boundary-min (4 edges x 25 linspace samples):
//   min over {X0,X1}x{y_k}  = min((px-X0)^2,(px-X1)^2) + min_k (py-y_k)^2
//   min over {x_k}x{Y0,Y1}  = min((py-Y0)^2,(py-Y1)^2) + min_k (px-x_k)^2
//
// R5: R2/R3/R4 all pinned at 8.0us regardless of MUFU count / occupancy /
// tail -> the invariant was the int<->float CONVERSION count (F2I/I2F/F2F,
// ~20cyc narrow-pipe ops) inside edge_min_sq. This version does the nearest-
// index search entirely in float: clamp -> magic-constant round-to-nearest
// (2 FADDs) -> float +-1 probes with fminf/fmaxf clamps. Zero conversions.

#define THREADS 256
#define MAX_BLOCKS 8192

__device__ float g_partial[MAX_BLOCKS];
__device__ unsigned int g_ticket = 0;   // atomicInc with wrap -> self-resetting

// min over k=0..24 of (p - (k*(1/24)*len + lo))^2, matching reference
// sampling (s_k = fmaf(k*(1/24), len, lo)). inv24len = 24/len precomputed.
// All-float: no F2I/I2F/F2F instructions.
__device__ __forceinline__ float edge_min_sq(float p, float lo, float len,
                                             float inv24len) {
    const float DB    = 1.0f / 24.0f;
    const float MAGIC = 12582912.0f;               // 1.5 * 2^23
    float tc = (p - lo) * inv24len;                // continuous nearest index
    // NaN/inf-safe clamp first (len==0 -> tc inf/NaN -> clamps into range)
    float tcc = fminf(fmaxf(tc, 0.0f), 24.0f);
    // round-to-nearest(-even) via magic constant: exact for [0, 2^22]
    float k0 = (tcc + MAGIC) - MAGIC;
    float best = 3.4e38f;
#pragma unroll
    for (int dk = -1; dk <= 1; ++dk) {
        float kf = fminf(fmaxf(k0 + (float)dk, 0.0f), 24.0f);  // compile-time dk
        float s = fmaf(kf * DB, len, lo);          // same formula as reference
        float dd = p - s;
        best = fminf(best, dd * dd);
    }
    return best;
}

__device__ __forceinline__ float block_reduce(float val, float* ws) {
    unsigned mask = 0xffffffffu;
#pragma unroll
    for (int o = 16; o > 0; o >>= 1)
        val += __shfl_down_sync(mask, val, o);
    int lane = threadIdx.x & 31;
    int wid  = threadIdx.x >> 5;
    if (lane == 0) ws[wid] = val;
    __syncthreads();
    float v = 0.0f;
    if (wid == 0) {
        v = (lane < THREADS / 32) ? ws[lane] : 0.0f;
#pragma unroll
        for (int o = (THREADS / 32) / 2; o > 0; o >>= 1)
            v += __shfl_down_sync(mask, v, o);
    }
    return v;   // valid in warp 0 lane 0
}

__global__ __launch_bounds__(THREADS)
void box_render_loss_fused(const float4* __restrict__ boxes,
                           const float4* __restrict__ targets,
                           float* __restrict__ out,
                           int ntasks, double scale, unsigned int nblocks) {
    int t = blockIdx.x * THREADS + threadIdx.x;
    float val = 0.0f;
    if (t < ntasks) {
        int ch  = t % 2;            // column half: fi in [5*ch, 5*ch+5)
        int row = (t / 2) % 10;     // fragment row -> px
        int d   = (t / 20) & 1;     // direction: 0 = box frags vs target, 1 = swap
        int b   = t / 40;           // pair index

        float4 A = boxes[b];
        float4 T = targets[b];
        float4 F = d ? T : A;       // fragment-source box
        float4 O = d ? A : T;       // other box

        const float DF = 1.0f / 9.0f;
        float fw = F.z - F.x, fh = F.w - F.y;
        float px = fmaf((float)row * DF, fw, F.x);   // (float)row: compile-time? row is runtime
        // note: row/ch are runtime ints -> 2 I2F per thread total; negligible.

        float ow = O.z - O.x, oh = O.w - O.y;
        float inv24w = 24.0f * __frcp_rn(ow);
        float inv24h = 24.0f * __frcp_rn(oh);
        float X1 = ow + O.x;        // 1*ow + O.x, exactly as reference computes it
        float Y1 = oh + O.y;

        // x-dependent terms, hoisted across the 5 py values
        bool in_x   = (px - O.x >= 0.0f) && (O.z - px >= 0.0f);
        float dx0 = px - O.x, dx1 = px - X1;
        float vert_x = fminf(dx0 * dx0, dx1 * dx1);        // vertical edges, x part
        float dxmin  = edge_min_sq(px, O.x, ow, inv24w);   // horizontal edges, x part

        float fi = (float)(ch * 5);                 // one I2F, then float counter
#pragma unroll
        for (int j = 0; j < 5; ++j) {
            float py = fmaf(fi * DF, fh, F.y);
            fi += 1.0f;
            bool inside = in_x && (py - O.y >= 0.0f) && (O.w - py >= 0.0f);
            if (!inside) {
                float dymin = edge_min_sq(py, O.y, oh, inv24h);
                float dy0 = py - O.y, dy1 = py - Y1;
                float horz = fminf(dy0 * dy0, dy1 * dy1) + dxmin;
                val += fminf(vert_x + dymin, horz);
            }
        }
    }

    __shared__ float ws[THREADS / 32];
    __shared__ bool  is_last;
    float bsum = block_reduce(val, ws);

    if (threadIdx.x == 0) {
        g_partial[blockIdx.x] = bsum;    // contention-free plain store
        __threadfence();                 // make it visible GPU-wide
        // wraps back to 0 at nblocks-1 -> self-resetting across graph replays
        unsigned int ticket = atomicInc(&g_ticket, nblocks - 1u);
        is_last = (ticket == nblocks - 1u);
    }
    __syncthreads();

    if (is_last) {
        // Every prior block fenced before its inc -> partials visible at L2.
        float v = 0.0f;
        for (unsigned int i = threadIdx.x; i < nblocks; i += THREADS)
            v += __ldcg(&g_partial[i]);
        __syncthreads();                 // ws reuse hazard
        float total = block_reduce(v, ws);
        if (threadIdx.x == 0)
            out[0] = (float)((double)total * scale);
    }
}

extern "C" void kernel_launch(void* const* d_in, const int* in_sizes, int n_in,
                              void* d_out, int out_size) {
    const float4* boxes   = (const float4*)d_in[0];
    const float4* targets = (const float4*)d_in[1];
    float* out = (float*)d_out;

    int B = in_sizes[0] / 4;                 // 4096
    int ntasks = B * 40;                     // 2 dir * 10 rows * 2 col-halves
    unsigned int nblocks = (unsigned int)((ntasks + THREADS - 1) / THREADS); // 640
    if (nblocks > MAX_BLOCKS) nblocks = MAX_BLOCKS;

    double scale = 1.0 / (2.0 * (double)B * 100.0);

    box_render_loss_fused<<<nblocks, THREADS>>>(boxes, targets, out,
                                                ntasks, scale, nblocks);
}